// round 17
// baseline (speedup 1.0000x reference)
#include <cuda_runtime.h>
#include <cstdint>

#define BB 64
#define NN 576
#define DD 768
#define KK 1024
#define NT 2
#define ROWS (BB * NN)           // 36864
#define NPAIR (BB * KK)          // 65536
#define OUT_MAIN (NPAIR * NT)    // 131072
#define NV4 (DD / 4)             // 192 float4 per row
#define BPB 6                    // blocks per batch
#define GRID (BB * BPB)          // 384 <= 444 co-residency @ 3 blocks/SM
#define RPSTAGE 8                // rows per stage (one per warp)
#define STAGE_BYTES (RPSTAGE * DD * 4)   // 24576
#define STAGE_F4 (RPSTAGE * NV4)         // 1536
#define NSTAGES 12               // 96 rows per block

// Dynamic smem layout (63504 B):
//   [0, 2*STAGE_BYTES)           : double-buffered z stages
//   [49152, 49152+12288)         : Wc weight table [4][NV4]
//   [61440, 61440+2048)          : s_pr idx pairs
//   [63488, 63488+16)            : 2 mbarriers
#define OFF_WC   (2 * STAGE_BYTES)
#define OFF_PR   (OFF_WC + 12288)
#define OFF_MBAR (OFF_PR + 2048)
#define SMEM_TOTAL (OFF_MBAR + 16)

__device__ float4 g_P[ROWS];
__device__ unsigned int g_done[BB];   // per-batch counters (generation-counted)

__device__ __forceinline__ void mbar_init(uint32_t a, uint32_t cnt) {
    asm volatile("mbarrier.init.shared.b64 [%0], %1;" :: "r"(a), "r"(cnt) : "memory");
}
__device__ __forceinline__ void mbar_expect_tx(uint32_t a, uint32_t bytes) {
    asm volatile("mbarrier.arrive.expect_tx.shared.b64 _, [%0], %1;"
                 :: "r"(a), "r"(bytes) : "memory");
}
__device__ __forceinline__ void bulk_copy(uint32_t dst, const void* src,
                                          uint32_t bytes, uint32_t mbar) {
    asm volatile(
        "cp.async.bulk.shared::cta.global.mbarrier::complete_tx::bytes "
        "[%0], [%1], %2, [%3];"
        :: "r"(dst), "l"(src), "r"(bytes), "r"(mbar) : "memory");
}
__device__ __forceinline__ void mbar_wait(uint32_t a, uint32_t parity) {
    uint32_t done;
    asm volatile(
        "{\n\t.reg .pred p;\n\t"
        "mbarrier.try_wait.parity.acquire.cta.shared::cta.b64 p, [%1], %2;\n\t"
        "selp.b32 %0, 1, 0, p;\n\t}"
        : "=r"(done) : "r"(a), "r"(parity) : "memory");
    if (!done) {
        asm volatile(
            "{\n\t.reg .pred P1;\n\t"
            "WL_%=:\n\t"
            "mbarrier.try_wait.parity.acquire.cta.shared::cta.b64 P1, [%0], %1, 0x989680;\n\t"
            "@P1 bra.uni WD_%=;\n\t"
            "bra.uni WL_%=;\n\t"
            "WD_%=:\n\t}"
            :: "r"(a), "r"(parity) : "memory");
    }
}

// Fused per-batch pipeline: TMA-bulk double-buffered projection -> per-batch
// barrier -> overlapped gather.
__global__ __launch_bounds__(256, 3) void partvit_fused_kernel(
    const float* __restrict__ z, const int* __restrict__ idx,
    const float* __restrict__ W, const float* __restrict__ bh,
    float* __restrict__ out, int out_size) {
    extern __shared__ char smem[];
    float4* Wc   = reinterpret_cast<float4*>(smem + OFF_WC);   // [4][NV4]
    int2*   s_pr = reinterpret_cast<int2*>(smem + OFF_PR);
    uint32_t sbase = (uint32_t)__cvta_generic_to_shared(smem);
    uint32_t mbar0 = sbase + OFF_MBAR;
    uint32_t mbar1 = sbase + OFF_MBAR + 8;

    int tid  = threadIdx.x;
    int lane = tid & 31;
    int w    = tid >> 5;
    int b    = blockIdx.x / BPB;     // batch
    int r    = blockIdx.x % BPB;     // block-in-batch (0..5)

    // ---- Init mbarriers, weights, idx prefetch ----
    if (tid == 0) { mbar_init(mbar0, 1); mbar_init(mbar1, 1); }
    for (int f = tid; f < DD; f += 256) {
        int c = f / NV4, i4 = f - c * NV4;
        int d = 4 * i4 + c;
        Wc[c * NV4 + i4] = make_float4(W[2 * d], W[2 * d + 1],
                                       W[2 * (d + DD)], W[2 * (d + DD) + 1]);
    }
    int gpair = b * KK + r * 256 + tid;    // valid when r < 4
    s_pr[tid] = (r < 4) ? reinterpret_cast<const int2*>(idx)[gpair]
                        : make_int2(0, 0);
    __syncthreads();

    // ---- Phase 1: TMA-bulk pipelined projection ----
    // Block covers rows [b*NN + r*96, +96) as 12 stages of 8 rows.
    const int row0 = b * NN + r * (NSTAGES * RPSTAGE);
    const float* zsrc0 = z + (size_t)row0 * DD;

    if (tid == 0) {
        // prologue: stages 0 and 1
        mbar_expect_tx(mbar0, STAGE_BYTES);
        bulk_copy(sbase + 0, zsrc0, STAGE_BYTES, mbar0);
        mbar_expect_tx(mbar1, STAGE_BYTES);
        bulk_copy(sbase + STAGE_BYTES, zsrc0 + STAGE_F4 * 4, STAGE_BYTES, mbar1);
    }

    #pragma unroll 1
    for (int s = 0; s < NSTAGES; s++) {
        uint32_t mb = (s & 1) ? mbar1 : mbar0;
        mbar_wait(mb, (s >> 1) & 1);

        // compute: warp w owns row s*8 + w of this block's range
        const float4* zr = reinterpret_cast<const float4*>(smem)
                           + (s & 1) * STAGE_F4 + w * NV4;
        float ax = 0.f, ay = 0.f, az = 0.f, aw = 0.f;
        #pragma unroll 1
        for (int j = 0; j < 6; j++) {
            int i4 = lane + 32 * j;
            float4 zv = zr[i4];                      // conflict-free LDS.128
            float4 w0 = Wc[0 * NV4 + i4];
            float4 w1 = Wc[1 * NV4 + i4];
            float4 w2 = Wc[2 * NV4 + i4];
            float4 w3 = Wc[3 * NV4 + i4];
            ax += zv.x*w0.x + zv.y*w1.x + zv.z*w2.x + zv.w*w3.x;
            ay += zv.x*w0.y + zv.y*w1.y + zv.z*w2.y + zv.w*w3.y;
            az += zv.x*w0.z + zv.y*w1.z + zv.z*w2.z + zv.w*w3.z;
            aw += zv.x*w0.w + zv.y*w1.w + zv.z*w2.w + zv.w*w3.w;
        }
        #pragma unroll
        for (int off = 16; off; off >>= 1) {
            ax += __shfl_xor_sync(0xffffffffu, ax, off);
            ay += __shfl_xor_sync(0xffffffffu, ay, off);
            az += __shfl_xor_sync(0xffffffffu, az, off);
            aw += __shfl_xor_sync(0xffffffffu, aw, off);
        }
        if (lane == 0)
            g_P[row0 + s * RPSTAGE + w] = make_float4(ax, ay, az, aw);

        __syncthreads();   // all warps done reading buf[s&1]
        if (s + 2 < NSTAGES && tid == 0) {
            uint32_t dst = sbase + (s & 1) * STAGE_BYTES;
            mbar_expect_tx(mb, STAGE_BYTES);
            bulk_copy(dst, zsrc0 + (size_t)(s + 2) * STAGE_F4 * 4,
                      STAGE_BYTES, mb);
        }
    }

    // ---- Per-batch barrier (generation-counted, replay-safe) ----
    __syncthreads();
    if (tid == 0) {
        __threadfence();                                  // release g_P writes
        unsigned old = atomicAdd(&g_done[b], 1u);
        unsigned target = (old / BPB) * BPB + BPB;        // this generation
        unsigned v;
        do {
            asm volatile("ld.global.acquire.gpu.u32 %0, [%1];"
                         : "=r"(v) : "l"(&g_done[b]));
            if ((int)(v - target) >= 0) break;
            __nanosleep(32);
        } while (true);
    }
    __syncthreads();

    // ---- Phase 2: gather this batch's pairs (blocks 0..3, 256 each) ----
    if (r >= 4) return;
    int2 pr = s_pr[tid];
    float bh0 = bh[0], bh1 = bh[1];                       // L2-hot
    int i0 = min(max(pr.x, 0), NN - 1);
    int i1 = min(max(pr.y, 0), NN - 1);

    float4 p0 = g_P[b * NN + i0];   // pair elem 0 -> W[0:D] halves (.x,.y)
    float4 p1 = g_P[b * NN + i1];   // pair elem 1 -> W[D:2D] halves (.z,.w)

    float2 o;
    o.x = p0.x + p1.z + bh0;
    o.y = p0.y + p1.w + bh1;
    reinterpret_cast<float2*>(out)[gpair] = o;

    // If the harness flattens the (out, indices) tuple, echo indices as f32.
    if (out_size >= OUT_MAIN + 2 * NPAIR) {
        out[OUT_MAIN + 2 * gpair + 0] = (float)pr.x;
        out[OUT_MAIN + 2 * gpair + 1] = (float)pr.y;
    }
}

extern "C" void kernel_launch(void* const* d_in, const int* in_sizes, int n_in,
                              void* d_out, int out_size) {
    const float* z   = (const float*)d_in[0];      // [B, N, D] f32
    const int*   idx = (const int*)d_in[1];        // [B, K, 2] i32
    const float* W   = (const float*)d_in[2];      // [2D, NT] f32
    const float* bh  = (const float*)d_in[3];      // [NT] f32
    float* out = (float*)d_out;

    static int configured = 0;
    if (!configured) {
        cudaFuncSetAttribute(partvit_fused_kernel,
                             cudaFuncAttributeMaxDynamicSharedMemorySize,
                             SMEM_TOTAL);
        configured = 1;
    }
    partvit_fused_kernel<<<GRID, 256, SMEM_TOTAL>>>(z, idx, W, bh, out, out_size);
}